// round 1
// baseline (speedup 1.0000x reference)
#include <cuda_runtime.h>
#include <cstdint>

#define NN 100000
#define EE 800000
#define IN_DIM 256
#define H 4
#define D 32
#define HD 128
#define SLOPE 0.2f

// ---------------- scratch (no allocations allowed) ----------------
__device__ float    g_feat[NN * HD];   // projected features of current layer
__device__ float    g_h1[NN * HD];     // layer-0 output (input + residual for layer 1)
__device__ float    g_agg[NN * HD];    // aggregation buffer
__device__ float    g_el[NN * H];
__device__ float    g_er[NN * H];
__device__ float    g_denom[NN * H];
__device__ unsigned g_emax[NN * H];    // uint-keyed float max
__device__ float    g_e0[EE * H];      // layer-0 raw scores

// monotonic float<->uint key for atomicMax on floats
__device__ __forceinline__ unsigned fenc(float x) {
    unsigned u = __float_as_uint(x);
    return (u & 0x80000000u) ? ~u : (u | 0x80000000u);
}
__device__ __forceinline__ float fdec(unsigned k) {
    return __uint_as_float((k & 0x80000000u) ? (k ^ 0x80000000u) : ~k);
}

__device__ __forceinline__ float elu1(float x) {
    return x > 0.f ? x : expm1f(x);
}

// ---------------- zero-fill ----------------
__global__ void zero_layer_kernel() {
    int i = blockIdx.x * blockDim.x + threadIdx.x;
    const int n_agg4 = NN * HD / 4;       // 3.2M
    const int n_nh4  = NN * H / 4;        // 100k
    if (i < n_agg4) ((float4*)g_agg)[i] = make_float4(0.f, 0.f, 0.f, 0.f);
    if (i < n_nh4) {
        ((float4*)g_denom)[i] = make_float4(0.f, 0.f, 0.f, 0.f);
        ((uint4*)g_emax)[i]   = make_uint4(0u, 0u, 0u, 0u);
    }
}

// ---------------- SGEMM: C[M,128] = A[M,K] @ B[K,128] ----------------
// 128x128 tile, 256 threads, 8x8 per thread, BK=16.
__global__ __launch_bounds__(256) void sgemm128(const float* __restrict__ A,
                                                const float* __restrict__ B,
                                                float* __restrict__ C,
                                                int M, int K) {
    __shared__ float As[16][128];
    __shared__ float Bs[16][128];
    int tid = threadIdx.x;
    int block_row = blockIdx.x * 128;
    int tx = tid & 15, ty = tid >> 4;

    float acc[8][8];
#pragma unroll
    for (int i = 0; i < 8; i++)
#pragma unroll
        for (int j = 0; j < 8; j++) acc[i][j] = 0.f;

    int a_row = tid & 127;
    int a_cg  = (tid >> 7) * 4;     // 0 or 4
    int b_row = tid >> 5;           // 0..7
    int b_col = (tid & 31) * 4;
    const float* Aptr = A + (size_t)(block_row + a_row) * K;
    bool a_valid = (block_row + a_row) < M;

    for (int kt = 0; kt < K; kt += 16) {
#pragma unroll
        for (int i = 0; i < 2; i++) {
            int kc = a_cg + i * 8;
            float4 v = a_valid ? *(const float4*)(Aptr + kt + kc)
                               : make_float4(0.f, 0.f, 0.f, 0.f);
            As[kc + 0][a_row] = v.x;
            As[kc + 1][a_row] = v.y;
            As[kc + 2][a_row] = v.z;
            As[kc + 3][a_row] = v.w;
        }
#pragma unroll
        for (int i = 0; i < 2; i++) {
            int kr = b_row + i * 8;
            *(float4*)&Bs[kr][b_col] = *(const float4*)(B + (size_t)(kt + kr) * 128 + b_col);
        }
        __syncthreads();
#pragma unroll
        for (int k = 0; k < 16; k++) {
            float av[8], bv[8];
            *(float4*)&av[0] = *(const float4*)&As[k][ty * 4];
            *(float4*)&av[4] = *(const float4*)&As[k][ty * 4 + 64];
            *(float4*)&bv[0] = *(const float4*)&Bs[k][tx * 4];
            *(float4*)&bv[4] = *(const float4*)&Bs[k][tx * 4 + 64];
#pragma unroll
            for (int i = 0; i < 8; i++)
#pragma unroll
                for (int j = 0; j < 8; j++)
                    acc[i][j] = fmaf(av[i], bv[j], acc[i][j]);
        }
        __syncthreads();
    }

#pragma unroll
    for (int gi = 0; gi < 2; gi++) {
#pragma unroll
        for (int ii = 0; ii < 4; ii++) {
            int r = block_row + gi * 64 + ty * 4 + ii;
            if (r < M) {
                float* crow = C + (size_t)r * 128;
                float4 v0 = make_float4(acc[gi * 4 + ii][0], acc[gi * 4 + ii][1],
                                        acc[gi * 4 + ii][2], acc[gi * 4 + ii][3]);
                float4 v1 = make_float4(acc[gi * 4 + ii][4], acc[gi * 4 + ii][5],
                                        acc[gi * 4 + ii][6], acc[gi * 4 + ii][7]);
                *(float4*)(crow + tx * 4)      = v0;
                *(float4*)(crow + 64 + tx * 4) = v1;
            }
        }
    }
}

// ---------------- per-(node,head) attention dots ----------------
__global__ void elr_kernel(const float* __restrict__ feat,
                           const float* __restrict__ al,
                           const float* __restrict__ ar) {
    int i = blockIdx.x * blockDim.x + threadIdx.x;
    if (i >= NN * H) return;
    int node = i >> 2, h = i & 3;
    const float* f = feat + (size_t)node * HD + h * D;
    const float* a = al + h * D;
    const float* r = ar + h * D;
    float sl = 0.f, sr = 0.f;
#pragma unroll
    for (int d = 0; d < D; d += 4) {
        float4 fv = *(const float4*)(f + d);
        float4 av = *(const float4*)(a + d);
        float4 rv = *(const float4*)(r + d);
        sl += fv.x * av.x + fv.y * av.y + fv.z * av.z + fv.w * av.w;
        sr += fv.x * rv.x + fv.y * rv.y + fv.z * rv.z + fv.w * rv.w;
    }
    g_el[i] = sl;
    g_er[i] = sr;
}

// ---------------- edge scores + segment max ----------------
__global__ void edge_score_kernel(const int* __restrict__ ei,
                                  float* __restrict__ ebuf,
                                  float* __restrict__ atten) {
    int e = blockIdx.x * blockDim.x + threadIdx.x;
    if (e >= EE) return;
    int s = ei[e], d = ei[EE + e];
    float4 l = *(const float4*)(g_el + (size_t)s * 4);
    float4 r = *(const float4*)(g_er + (size_t)d * 4);
    float z0 = l.x + r.x, z1 = l.y + r.y, z2 = l.z + r.z, z3 = l.w + r.w;
    z0 = z0 > 0.f ? z0 : SLOPE * z0;
    z1 = z1 > 0.f ? z1 : SLOPE * z1;
    z2 = z2 > 0.f ? z2 : SLOPE * z2;
    z3 = z3 > 0.f ? z3 : SLOPE * z3;
    *(float4*)(ebuf + (size_t)e * 4) = make_float4(z0, z1, z2, z3);
    atten[e] = 0.25f * (z0 + z1 + z2 + z3);
    unsigned* em = g_emax + (size_t)d * 4;
    atomicMax(em + 0, fenc(z0));
    atomicMax(em + 1, fenc(z1));
    atomicMax(em + 2, fenc(z2));
    atomicMax(em + 3, fenc(z3));
}

// ---------------- exp + segment sum ----------------
__global__ void edge_expsum_kernel(const int* __restrict__ ei,
                                   const float* __restrict__ ebuf) {
    int e = blockIdx.x * blockDim.x + threadIdx.x;
    if (e >= EE) return;
    int d = ei[EE + e];
    float4 z = *(const float4*)(ebuf + (size_t)e * 4);
    uint4 mk = *(const uint4*)(g_emax + (size_t)d * 4);
    float e0 = __expf(z.x - fdec(mk.x));
    float e1 = __expf(z.y - fdec(mk.y));
    float e2 = __expf(z.z - fdec(mk.z));
    float e3 = __expf(z.w - fdec(mk.w));
    float* dn = g_denom + (size_t)d * 4;
    asm volatile("red.global.add.v4.f32 [%0], {%1,%2,%3,%4};"
                 :: "l"(dn), "f"(e0), "f"(e1), "f"(e2), "f"(e3) : "memory");
}

// ---------------- weighted scatter: one warp per edge ----------------
__global__ void edge_scatter_kernel(const int* __restrict__ ei,
                                    const float* __restrict__ ebuf,
                                    const float* __restrict__ feat) {
    int gtid = blockIdx.x * blockDim.x + threadIdx.x;
    int e = gtid >> 5;
    int lane = gtid & 31;
    if (e >= EE) return;
    int s = ei[e], d = ei[EE + e];
    float4 z  = *(const float4*)(ebuf + (size_t)e * 4);
    uint4  mk = *(const uint4*)(g_emax + (size_t)d * 4);
    float4 dn = *(const float4*)(g_denom + (size_t)d * 4);
    int h = lane >> 3;
    float zh = (h == 0) ? z.x : (h == 1) ? z.y : (h == 2) ? z.z : z.w;
    unsigned mh = (h == 0) ? mk.x : (h == 1) ? mk.y : (h == 2) ? mk.z : mk.w;
    float dh = (h == 0) ? dn.x : (h == 1) ? dn.y : (h == 2) ? dn.z : dn.w;
    float a = __expf(zh - fdec(mh)) / dh;
    float4 f = *(const float4*)(feat + (size_t)s * HD + lane * 4);
    float m0 = f.x * a, m1 = f.y * a, m2 = f.z * a, m3 = f.w * a;
    float* dst = g_agg + (size_t)d * HD + lane * 4;
    asm volatile("red.global.add.v4.f32 [%0], {%1,%2,%3,%4};"
                 :: "l"(dst), "f"(m0), "f"(m1), "f"(m2), "f"(m3) : "memory");
}

// ---------------- layer-0 finalize: h1 = elu(agg) ----------------
__global__ void finalize0_kernel() {
    int j = blockIdx.x * blockDim.x + threadIdx.x;
    if (j >= NN * HD / 4) return;
    float4 v = ((const float4*)g_agg)[j];
    v.x = elu1(v.x); v.y = elu1(v.y); v.z = elu1(v.z); v.w = elu1(v.w);
    ((float4*)g_h1)[j] = v;
}

// ---------------- layer-1 finalize: temp + per-head outputs ----------------
__global__ void finalize1_kernel(float* __restrict__ out) {
    int j = blockIdx.x * blockDim.x + threadIdx.x;
    if (j >= NN * HD / 4) return;
    float4 v = ((const float4*)g_agg)[j];
    float4 r = ((const float4*)g_h1)[j];
    v.x = elu1(v.x + r.x); v.y = elu1(v.y + r.y);
    v.z = elu1(v.z + r.z); v.w = elu1(v.w + r.w);
    ((float4*)out)[j] = v;                     // temp [N, 128]
    int fi = j * 4;
    int node = fi >> 7;
    int rem = fi & 127;
    int h = rem >> 5;
    int d = rem & 31;
    float* headp = out + (size_t)NN * HD + (size_t)h * NN * D + (size_t)node * D + d;
    *(float4*)headp = v;
}

static inline int cdiv(int a, int b) { return (a + b - 1) / b; }

extern "C" void kernel_launch(void* const* d_in, const int* in_sizes, int n_in,
                              void* d_out, int out_size) {
    const float* x   = (const float*)d_in[0];
    const int*   ei  = (const int*)d_in[1];
    const float* W0  = (const float*)d_in[2];
    const float* al0 = (const float*)d_in[3];
    const float* ar0 = (const float*)d_in[4];
    const float* W1  = (const float*)d_in[5];
    const float* al1 = (const float*)d_in[6];
    const float* ar1 = (const float*)d_in[7];
    float* out = (float*)d_out;

    float* e1_out  = out + (size_t)NN * HD + (size_t)H * NN * D;  // [E, H]
    float* atten0  = e1_out + (size_t)EE * H;                     // [E]
    float* atten1  = atten0 + EE;                                 // [E]

    void *p_feat, *p_h1, *p_e0;
    cudaGetSymbolAddress(&p_feat, g_feat);
    cudaGetSymbolAddress(&p_h1, g_h1);
    cudaGetSymbolAddress(&p_e0, g_e0);
    float* feat = (float*)p_feat;
    float* h1   = (float*)p_h1;
    float* e0   = (float*)p_e0;

    const int T = 256;
    int g_zero  = cdiv(NN * HD / 4, T);
    int g_gemm  = cdiv(NN, 128);
    int g_elr   = cdiv(NN * H, T);
    int g_edge  = cdiv(EE, T);
    int g_scat  = cdiv(EE * 32, T);
    int g_fin   = cdiv(NN * HD / 4, T);

    // ---------- layer 0 ----------
    zero_layer_kernel<<<g_zero, T>>>();
    sgemm128<<<g_gemm, T>>>(x, W0, feat, NN, IN_DIM);
    elr_kernel<<<g_elr, T>>>(feat, al0, ar0);
    edge_score_kernel<<<g_edge, T>>>(ei, e0, atten0);
    edge_expsum_kernel<<<g_edge, T>>>(ei, e0);
    edge_scatter_kernel<<<g_scat, T>>>(ei, e0, feat);
    finalize0_kernel<<<g_fin, T>>>();

    // ---------- layer 1 ----------
    zero_layer_kernel<<<g_zero, T>>>();
    sgemm128<<<g_gemm, T>>>(h1, W1, feat, NN, HD);
    elr_kernel<<<g_elr, T>>>(feat, al1, ar1);
    edge_score_kernel<<<g_edge, T>>>(ei, e1_out, atten1);
    edge_expsum_kernel<<<g_edge, T>>>(ei, e1_out);
    edge_scatter_kernel<<<g_scat, T>>>(ei, e1_out, feat);
    finalize1_kernel<<<g_fin, T>>>(out);
}

// round 2
// speedup vs baseline: 1.3156x; 1.3156x over previous
#include <cuda_runtime.h>
#include <cstdint>

#define NN 100000
#define EE 800000
#define IN_DIM 256
#define H 4
#define D 32
#define HD 128
#define SLOPE 0.2f

// ---------------- scratch (no allocations allowed) ----------------
__device__ float    g_feat[NN * HD];   // projected features of current layer
__device__ float    g_h1[NN * HD];     // layer-0 output (residual for layer 1)
__device__ float    g_agg[NN * HD];    // UNNORMALIZED aggregation buffer
__device__ float    g_el[NN * H];
__device__ float    g_er[NN * H];
__device__ float    g_denom[NN * H];
__device__ unsigned g_emax[NN * H];    // uint-keyed float max
__device__ float    g_e0[EE * H];      // layer-0 raw scores

// monotonic float<->uint key for atomicMax on floats
__device__ __forceinline__ unsigned fenc(float x) {
    unsigned u = __float_as_uint(x);
    return (u & 0x80000000u) ? ~u : (u | 0x80000000u);
}
__device__ __forceinline__ float fdec(unsigned k) {
    return __uint_as_float((k & 0x80000000u) ? (k ^ 0x80000000u) : ~k);
}

__device__ __forceinline__ float elu1(float x) {
    return x > 0.f ? x : expm1f(x);
}

__device__ __forceinline__ float tf32r(float x) {
    uint32_t u;
    asm("cvt.rna.tf32.f32 %0, %1;" : "=r"(u) : "f"(x));
    return __uint_as_float(u);
}

// ---------------- zero-fill (split so ncu -s 5 lands on edge_scatter) ---
__global__ void zero_agg_kernel() {
    int i = blockIdx.x * blockDim.x + threadIdx.x;
    if (i < NN * HD / 4) ((float4*)g_agg)[i] = make_float4(0.f, 0.f, 0.f, 0.f);
}
__global__ void zero_nh_kernel() {
    int i = blockIdx.x * blockDim.x + threadIdx.x;
    if (i < NN * H / 4) {
        ((float4*)g_denom)[i] = make_float4(0.f, 0.f, 0.f, 0.f);
        ((uint4*)g_emax)[i]   = make_uint4(0u, 0u, 0u, 0u);
    }
}

// ---------------- TF32 tensor-core GEMM: C[M,128] = A[M,K] @ B[K,128] ----
// 128x128 block tile, 8 warps (2x4), warp tile 64x32, mma m16n8k8 tf32,
// BK=16, double-buffered smem. Pads: As stride 20, Bs stride 136 (bank-free
// fragment loads).
#define AS_S 20
#define BS_S 136

__global__ __launch_bounds__(256, 2) void sgemm_tf32(const float* __restrict__ A,
                                                     const float* __restrict__ B,
                                                     float* __restrict__ C,
                                                     int M, int K) {
    __shared__ float As[2][128][AS_S];
    __shared__ float Bs[2][16][BS_S];
    int tid = threadIdx.x;
    int lane = tid & 31;
    int wid = tid >> 5;
    int warp_m = wid & 1;      // 0..1  -> 64 rows each
    int warp_n = wid >> 1;     // 0..3  -> 32 cols each
    int block_row = blockIdx.x * 128;

    float c[4][4][4];
#pragma unroll
    for (int i = 0; i < 4; i++)
#pragma unroll
        for (int j = 0; j < 4; j++)
#pragma unroll
            for (int k = 0; k < 4; k++) c[i][j][k] = 0.f;

    int ar = tid >> 2;           // 0..63 (A row within tile; +64 second)
    int ac = (tid & 3) * 4;      // 0,4,8,12 (A col within BK)
    int br = tid >> 5;           // 0..7   (B row within BK; +8 second)
    int bc = (tid & 31) * 4;     // 0..124 (B col)

    int gr0 = block_row + ar;
    int gr1 = gr0 + 64;
    bool v0 = gr0 < M, v1 = gr1 < M;
    const float* Ap0 = A + (size_t)gr0 * K;
    const float* Ap1 = A + (size_t)gr1 * K;

    int ntiles = K >> 4;

    float4 pa0, pa1, pb0, pb1;
    // load tile 0
    {
        pa0 = v0 ? *(const float4*)(Ap0 + ac) : make_float4(0, 0, 0, 0);
        pa1 = v1 ? *(const float4*)(Ap1 + ac) : make_float4(0, 0, 0, 0);
        pb0 = *(const float4*)(B + (size_t)br * 128 + bc);
        pb1 = *(const float4*)(B + (size_t)(br + 8) * 128 + bc);
        float* as0 = &As[0][ar][ac];
        as0[0] = tf32r(pa0.x); as0[1] = tf32r(pa0.y);
        as0[2] = tf32r(pa0.z); as0[3] = tf32r(pa0.w);
        float* as1 = &As[0][ar + 64][ac];
        as1[0] = tf32r(pa1.x); as1[1] = tf32r(pa1.y);
        as1[2] = tf32r(pa1.z); as1[3] = tf32r(pa1.w);
        float* bs0 = &Bs[0][br][bc];
        bs0[0] = tf32r(pb0.x); bs0[1] = tf32r(pb0.y);
        bs0[2] = tf32r(pb0.z); bs0[3] = tf32r(pb0.w);
        float* bs1 = &Bs[0][br + 8][bc];
        bs1[0] = tf32r(pb1.x); bs1[1] = tf32r(pb1.y);
        bs1[2] = tf32r(pb1.z); bs1[3] = tf32r(pb1.w);
    }
    __syncthreads();

    int buf = 0;
    for (int kt = 0; kt < ntiles; kt++) {
        bool more = (kt + 1) < ntiles;
        if (more) {
            int kb = (kt + 1) * 16;
            pa0 = v0 ? *(const float4*)(Ap0 + kb + ac) : make_float4(0, 0, 0, 0);
            pa1 = v1 ? *(const float4*)(Ap1 + kb + ac) : make_float4(0, 0, 0, 0);
            pb0 = *(const float4*)(B + (size_t)(kb + br) * 128 + bc);
            pb1 = *(const float4*)(B + (size_t)(kb + br + 8) * 128 + bc);
        }
#pragma unroll
        for (int ks = 0; ks < 2; ks++) {
            int k8 = ks * 8;
            uint32_t af[4][4];
            uint32_t bf[4][2];
#pragma unroll
            for (int mi = 0; mi < 4; mi++) {
                int r = warp_m * 64 + mi * 16 + (lane >> 2);
                int kc = k8 + (lane & 3);
                af[mi][0] = __float_as_uint(As[buf][r][kc]);
                af[mi][1] = __float_as_uint(As[buf][r + 8][kc]);
                af[mi][2] = __float_as_uint(As[buf][r][kc + 4]);
                af[mi][3] = __float_as_uint(As[buf][r + 8][kc + 4]);
            }
#pragma unroll
            for (int nj = 0; nj < 4; nj++) {
                int cc = warp_n * 32 + nj * 8 + (lane >> 2);
                int kr = k8 + (lane & 3);
                bf[nj][0] = __float_as_uint(Bs[buf][kr][cc]);
                bf[nj][1] = __float_as_uint(Bs[buf][kr + 4][cc]);
            }
#pragma unroll
            for (int mi = 0; mi < 4; mi++)
#pragma unroll
                for (int nj = 0; nj < 4; nj++) {
                    asm("mma.sync.aligned.m16n8k8.row.col.f32.tf32.tf32.f32 "
                        "{%0,%1,%2,%3}, {%4,%5,%6,%7}, {%8,%9}, {%0,%1,%2,%3};"
                        : "+f"(c[mi][nj][0]), "+f"(c[mi][nj][1]),
                          "+f"(c[mi][nj][2]), "+f"(c[mi][nj][3])
                        : "r"(af[mi][0]), "r"(af[mi][1]),
                          "r"(af[mi][2]), "r"(af[mi][3]),
                          "r"(bf[nj][0]), "r"(bf[nj][1]));
                }
        }
        if (more) {
            int nb = buf ^ 1;
            float* as0 = &As[nb][ar][ac];
            as0[0] = tf32r(pa0.x); as0[1] = tf32r(pa0.y);
            as0[2] = tf32r(pa0.z); as0[3] = tf32r(pa0.w);
            float* as1 = &As[nb][ar + 64][ac];
            as1[0] = tf32r(pa1.x); as1[1] = tf32r(pa1.y);
            as1[2] = tf32r(pa1.z); as1[3] = tf32r(pa1.w);
            float* bs0 = &Bs[nb][br][bc];
            bs0[0] = tf32r(pb0.x); bs0[1] = tf32r(pb0.y);
            bs0[2] = tf32r(pb0.z); bs0[3] = tf32r(pb0.w);
            float* bs1 = &Bs[nb][br + 8][bc];
            bs1[0] = tf32r(pb1.x); bs1[1] = tf32r(pb1.y);
            bs1[2] = tf32r(pb1.z); bs1[3] = tf32r(pb1.w);
        }
        __syncthreads();
        buf ^= 1;
    }

    // epilogue
#pragma unroll
    for (int mi = 0; mi < 4; mi++) {
#pragma unroll
        for (int nj = 0; nj < 4; nj++) {
            int row0 = block_row + warp_m * 64 + mi * 16 + (lane >> 2);
            int col = warp_n * 32 + nj * 8 + (lane & 3) * 2;
            if (row0 < M)
                *(float2*)(C + (size_t)row0 * 128 + col) =
                    make_float2(c[mi][nj][0], c[mi][nj][1]);
            int row1 = row0 + 8;
            if (row1 < M)
                *(float2*)(C + (size_t)row1 * 128 + col) =
                    make_float2(c[mi][nj][2], c[mi][nj][3]);
        }
    }
}

// ---------------- per-(node,head) attention dots ----------------
__global__ void elr_kernel(const float* __restrict__ feat,
                           const float* __restrict__ al,
                           const float* __restrict__ ar) {
    int i = blockIdx.x * blockDim.x + threadIdx.x;
    if (i >= NN * H) return;
    int node = i >> 2, h = i & 3;
    const float* f = feat + (size_t)node * HD + h * D;
    const float* a = al + h * D;
    const float* r = ar + h * D;
    float sl = 0.f, sr = 0.f;
#pragma unroll
    for (int d = 0; d < D; d += 4) {
        float4 fv = *(const float4*)(f + d);
        float4 av = *(const float4*)(a + d);
        float4 rv = *(const float4*)(r + d);
        sl += fv.x * av.x + fv.y * av.y + fv.z * av.z + fv.w * av.w;
        sr += fv.x * rv.x + fv.y * rv.y + fv.z * rv.z + fv.w * rv.w;
    }
    g_el[i] = sl;
    g_er[i] = sr;
}

// ---------------- edge scores + segment max ----------------
__global__ void edge_score_kernel(const int* __restrict__ ei,
                                  float* __restrict__ ebuf,
                                  float* __restrict__ atten) {
    int e = blockIdx.x * blockDim.x + threadIdx.x;
    if (e >= EE) return;
    int s = ei[e], d = ei[EE + e];
    float4 l = *(const float4*)(g_el + (size_t)s * 4);
    float4 r = *(const float4*)(g_er + (size_t)d * 4);
    float z0 = l.x + r.x, z1 = l.y + r.y, z2 = l.z + r.z, z3 = l.w + r.w;
    z0 = z0 > 0.f ? z0 : SLOPE * z0;
    z1 = z1 > 0.f ? z1 : SLOPE * z1;
    z2 = z2 > 0.f ? z2 : SLOPE * z2;
    z3 = z3 > 0.f ? z3 : SLOPE * z3;
    *(float4*)(ebuf + (size_t)e * 4) = make_float4(z0, z1, z2, z3);
    atten[e] = 0.25f * (z0 + z1 + z2 + z3);
    unsigned* em = g_emax + (size_t)d * 4;
    atomicMax(em + 0, fenc(z0));
    atomicMax(em + 1, fenc(z1));
    atomicMax(em + 2, fenc(z2));
    atomicMax(em + 3, fenc(z3));
}

// ---------------- fused exp + denom + weighted scatter (unnormalized) ----
// one warp per edge; head h = lane>>3, 4 feats per lane.
__global__ void edge_scatter_kernel(const int* __restrict__ ei,
                                    const float* __restrict__ ebuf,
                                    const float* __restrict__ feat) {
    int gtid = blockIdx.x * blockDim.x + threadIdx.x;
    int e = gtid >> 5;
    int lane = gtid & 31;
    if (e >= EE) return;
    int s = ei[e], d = ei[EE + e];
    float4 z  = *(const float4*)(ebuf + (size_t)e * 4);
    uint4  mk = *(const uint4*)(g_emax + (size_t)d * 4);
    int h = lane >> 3;
    float zh = (h == 0) ? z.x : (h == 1) ? z.y : (h == 2) ? z.z : z.w;
    unsigned mh = (h == 0) ? mk.x : (h == 1) ? mk.y : (h == 2) ? mk.z : mk.w;
    float ex = __expf(zh - fdec(mh));
    if ((lane & 7) == 0) {
        float* dn = g_denom + (size_t)d * 4 + h;
        asm volatile("red.global.add.f32 [%0], %1;" :: "l"(dn), "f"(ex) : "memory");
    }
    float4 f = *(const float4*)(feat + (size_t)s * HD + lane * 4);
    float m0 = f.x * ex, m1 = f.y * ex, m2 = f.z * ex, m3 = f.w * ex;
    float* dst = g_agg + (size_t)d * HD + lane * 4;
    asm volatile("red.global.add.v4.f32 [%0], {%1,%2,%3,%4};"
                 :: "l"(dst), "f"(m0), "f"(m1), "f"(m2), "f"(m3) : "memory");
}

// ---------------- layer-0 finalize: h1 = elu(agg/denom) ----------------
__global__ void finalize0_kernel() {
    int j = blockIdx.x * blockDim.x + threadIdx.x;
    if (j >= NN * HD / 4) return;
    int fi = j * 4;
    int node = fi >> 7;
    int h = (fi >> 5) & 3;
    float dn = g_denom[(size_t)node * 4 + h];
    float inv = dn > 0.f ? 1.f / dn : 0.f;
    float4 v = ((const float4*)g_agg)[j];
    v.x = elu1(v.x * inv); v.y = elu1(v.y * inv);
    v.z = elu1(v.z * inv); v.w = elu1(v.w * inv);
    ((float4*)g_h1)[j] = v;
}

// ---------------- layer-1 finalize: temp + per-head outputs ----------------
__global__ void finalize1_kernel(float* __restrict__ out) {
    int j = blockIdx.x * blockDim.x + threadIdx.x;
    if (j >= NN * HD / 4) return;
    int fi = j * 4;
    int node = fi >> 7;
    int rem = fi & 127;
    int h = rem >> 5;
    int d = rem & 31;
    float dn = g_denom[(size_t)node * 4 + h];
    float inv = dn > 0.f ? 1.f / dn : 0.f;
    float4 v = ((const float4*)g_agg)[j];
    float4 r = ((const float4*)g_h1)[j];
    v.x = elu1(v.x * inv + r.x); v.y = elu1(v.y * inv + r.y);
    v.z = elu1(v.z * inv + r.z); v.w = elu1(v.w * inv + r.w);
    ((float4*)out)[j] = v;                     // temp [N, 128]
    float* headp = out + (size_t)NN * HD + (size_t)h * NN * D + (size_t)node * D + d;
    *(float4*)headp = v;
}

static inline int cdiv(int a, int b) { return (a + b - 1) / b; }

extern "C" void kernel_launch(void* const* d_in, const int* in_sizes, int n_in,
                              void* d_out, int out_size) {
    const float* x   = (const float*)d_in[0];
    const int*   ei  = (const int*)d_in[1];
    const float* W0  = (const float*)d_in[2];
    const float* al0 = (const float*)d_in[3];
    const float* ar0 = (const float*)d_in[4];
    const float* W1  = (const float*)d_in[5];
    const float* al1 = (const float*)d_in[6];
    const float* ar1 = (const float*)d_in[7];
    float* out = (float*)d_out;

    float* e1_out  = out + (size_t)NN * HD + (size_t)H * NN * D;  // [E, H]
    float* atten0  = e1_out + (size_t)EE * H;                     // [E]
    float* atten1  = atten0 + EE;                                 // [E]

    void *p_feat, *p_h1, *p_e0;
    cudaGetSymbolAddress(&p_feat, g_feat);
    cudaGetSymbolAddress(&p_h1, g_h1);
    cudaGetSymbolAddress(&p_e0, g_e0);
    float* feat = (float*)p_feat;
    float* h1   = (float*)p_h1;
    float* e0   = (float*)p_e0;

    const int T = 256;
    int g_zagg  = cdiv(NN * HD / 4, T);
    int g_znh   = cdiv(NN * H / 4, T);
    int g_gemm  = cdiv(NN, 128);
    int g_elr   = cdiv(NN * H, T);
    int g_edge  = cdiv(EE, T);
    int g_scat  = cdiv(EE * 32, T);
    int g_fin   = cdiv(NN * HD / 4, T);

    // ---------- layer 0 ----------
    zero_agg_kernel<<<g_zagg, T>>>();
    zero_nh_kernel<<<g_znh, T>>>();
    sgemm_tf32<<<g_gemm, T>>>(x, W0, feat, NN, IN_DIM);
    elr_kernel<<<g_elr, T>>>(feat, al0, ar0);
    edge_score_kernel<<<g_edge, T>>>(ei, e0, atten0);
    edge_scatter_kernel<<<g_scat, T>>>(ei, e0, feat);   // <- profiled launch (#6)
    finalize0_kernel<<<g_fin, T>>>();

    // ---------- layer 1 ----------
    zero_agg_kernel<<<g_zagg, T>>>();
    zero_nh_kernel<<<g_znh, T>>>();
    sgemm_tf32<<<g_gemm, T>>>(h1, W1, feat, NN, HD);
    elr_kernel<<<g_elr, T>>>(feat, al1, ar1);
    edge_score_kernel<<<g_edge, T>>>(ei, e1_out, atten1);
    edge_scatter_kernel<<<g_scat, T>>>(ei, e1_out, feat);
    finalize1_kernel<<<g_fin, T>>>(out);
}

// round 3
// speedup vs baseline: 2.2784x; 1.7318x over previous
#include <cuda_runtime.h>
#include <cstdint>

#define NN 100000
#define EE 800000
#define IN_DIM 256
#define H 4
#define D 32
#define HD 128
#define SLOPE 0.2f
#define NINF (-3.402823466e38f)

// ---------------- scratch (no allocations allowed) ----------------
__device__ float g_feat[NN * HD];     // projected features of current layer
__device__ float g_h1[NN * HD];       // layer-0 output (residual for layer 1)
__device__ float g_el[NN * H];
__device__ float g_er[NN * H];
__device__ float g_e0[EE * H];        // layer-0 raw scores
__device__ int   g_deg[NN];
__device__ int   g_rowptr[NN + 1];
__device__ int   g_cursor[NN];
__device__ int   g_partial[256];
__device__ int   g_csr_src[EE];
__device__ int   g_csr_eid[EE];

__device__ __forceinline__ float elu1(float x) {
    return x > 0.f ? x : expm1f(x);
}
__device__ __forceinline__ float tf32r(float x) {
    uint32_t u;
    asm("cvt.rna.tf32.f32 %0, %1;" : "=r"(u) : "f"(x));
    return __uint_as_float(u);
}

// ================= CSR build =================
__global__ void zero_deg_kernel() {
    int i = blockIdx.x * blockDim.x + threadIdx.x;
    if (i < NN) g_deg[i] = 0;
}

__global__ void count_deg_kernel(const int* __restrict__ ei) {
    int e = blockIdx.x * blockDim.x + threadIdx.x;
    if (e < EE) atomicAdd(&g_deg[ei[EE + e]], 1);
}

#define SCAN_BS 512
#define NBLK1 ((NN + SCAN_BS - 1) / SCAN_BS)   // 196

__global__ __launch_bounds__(SCAN_BS) void scan1_kernel() {
    __shared__ int s[SCAN_BS];
    int t = threadIdx.x;
    int i = blockIdx.x * SCAN_BS + t;
    int v = (i < NN) ? g_deg[i] : 0;
    s[t] = v;
    __syncthreads();
#pragma unroll
    for (int off = 1; off < SCAN_BS; off <<= 1) {
        int x = (t >= off) ? s[t - off] : 0;
        __syncthreads();
        s[t] += x;
        __syncthreads();
    }
    if (i < NN) g_rowptr[i] = s[t] - v;      // exclusive within block
    if (t == SCAN_BS - 1) g_partial[blockIdx.x] = s[t];
}

__global__ __launch_bounds__(256) void scan2_kernel() {
    __shared__ int s[256];
    int t = threadIdx.x;
    int v = (t < NBLK1) ? g_partial[t] : 0;
    s[t] = v;
    __syncthreads();
#pragma unroll
    for (int off = 1; off < 256; off <<= 1) {
        int x = (t >= off) ? s[t - off] : 0;
        __syncthreads();
        s[t] += x;
        __syncthreads();
    }
    if (t < NBLK1) g_partial[t] = s[t] - v;  // exclusive across blocks
}

__global__ __launch_bounds__(SCAN_BS) void scan3_kernel() {
    int t = threadIdx.x;
    int i = blockIdx.x * SCAN_BS + t;
    if (i < NN) {
        int r = g_rowptr[i] + g_partial[blockIdx.x];
        g_rowptr[i] = r;
        g_cursor[i] = r;
    }
    if (i == 0) g_rowptr[NN] = EE;
}

__global__ void fill_csr_kernel(const int* __restrict__ ei) {
    int e = blockIdx.x * blockDim.x + threadIdx.x;
    if (e >= EE) return;
    int s = ei[e], d = ei[EE + e];
    int pos = atomicAdd(&g_cursor[d], 1);
    g_csr_src[pos] = s;
    g_csr_eid[pos] = e;
}

// ========== TF32 tensor-core GEMM fused with attention dots ==========
// C[M,128] = A[M,K] @ B[K,128]; epilogue also computes
// el[r,h] = dot(C[r, h*32:(h+1)*32], al[h]), er likewise. One warp owns
// one head's 32-column group -> quad shfl reduction, no atomics.
#define AS_S 20
#define BS_S 136

__global__ __launch_bounds__(256, 2) void sgemm_tf32(const float* __restrict__ A,
                                                     const float* __restrict__ B,
                                                     const float* __restrict__ al,
                                                     const float* __restrict__ ar,
                                                     float* __restrict__ C,
                                                     int M, int K) {
    __shared__ float As[2][128][AS_S];
    __shared__ float Bs[2][16][BS_S];
    int tid = threadIdx.x;
    int lane = tid & 31;
    int wid = tid >> 5;
    int warp_m = wid & 1;
    int warp_n = wid >> 1;
    int block_row = blockIdx.x * 128;

    float c[4][4][4];
#pragma unroll
    for (int i = 0; i < 4; i++)
#pragma unroll
        for (int j = 0; j < 4; j++)
#pragma unroll
            for (int k = 0; k < 4; k++) c[i][j][k] = 0.f;

    int ar_r = tid >> 2;
    int ac = (tid & 3) * 4;
    int br = tid >> 5;
    int bc = (tid & 31) * 4;

    int gr0 = block_row + ar_r;
    int gr1 = gr0 + 64;
    bool v0 = gr0 < M, v1 = gr1 < M;
    const float* Ap0 = A + (size_t)gr0 * K;
    const float* Ap1 = A + (size_t)gr1 * K;

    int ntiles = K >> 4;
    float4 pa0, pa1, pb0, pb1;
    {
        pa0 = v0 ? *(const float4*)(Ap0 + ac) : make_float4(0, 0, 0, 0);
        pa1 = v1 ? *(const float4*)(Ap1 + ac) : make_float4(0, 0, 0, 0);
        pb0 = *(const float4*)(B + (size_t)br * 128 + bc);
        pb1 = *(const float4*)(B + (size_t)(br + 8) * 128 + bc);
        float* as0 = &As[0][ar_r][ac];
        as0[0] = tf32r(pa0.x); as0[1] = tf32r(pa0.y);
        as0[2] = tf32r(pa0.z); as0[3] = tf32r(pa0.w);
        float* as1 = &As[0][ar_r + 64][ac];
        as1[0] = tf32r(pa1.x); as1[1] = tf32r(pa1.y);
        as1[2] = tf32r(pa1.z); as1[3] = tf32r(pa1.w);
        float* bs0 = &Bs[0][br][bc];
        bs0[0] = tf32r(pb0.x); bs0[1] = tf32r(pb0.y);
        bs0[2] = tf32r(pb0.z); bs0[3] = tf32r(pb0.w);
        float* bs1 = &Bs[0][br + 8][bc];
        bs1[0] = tf32r(pb1.x); bs1[1] = tf32r(pb1.y);
        bs1[2] = tf32r(pb1.z); bs1[3] = tf32r(pb1.w);
    }
    __syncthreads();

    int buf = 0;
    for (int kt = 0; kt < ntiles; kt++) {
        bool more = (kt + 1) < ntiles;
        if (more) {
            int kb = (kt + 1) * 16;
            pa0 = v0 ? *(const float4*)(Ap0 + kb + ac) : make_float4(0, 0, 0, 0);
            pa1 = v1 ? *(const float4*)(Ap1 + kb + ac) : make_float4(0, 0, 0, 0);
            pb0 = *(const float4*)(B + (size_t)(kb + br) * 128 + bc);
            pb1 = *(const float4*)(B + (size_t)(kb + br + 8) * 128 + bc);
        }
#pragma unroll
        for (int ks = 0; ks < 2; ks++) {
            int k8 = ks * 8;
            uint32_t af[4][4];
            uint32_t bf[4][2];
#pragma unroll
            for (int mi = 0; mi < 4; mi++) {
                int r = warp_m * 64 + mi * 16 + (lane >> 2);
                int kc = k8 + (lane & 3);
                af[mi][0] = __float_as_uint(As[buf][r][kc]);
                af[mi][1] = __float_as_uint(As[buf][r + 8][kc]);
                af[mi][2] = __float_as_uint(As[buf][r][kc + 4]);
                af[mi][3] = __float_as_uint(As[buf][r + 8][kc + 4]);
            }
#pragma unroll
            for (int nj = 0; nj < 4; nj++) {
                int cc = warp_n * 32 + nj * 8 + (lane >> 2);
                int kr = k8 + (lane & 3);
                bf[nj][0] = __float_as_uint(Bs[buf][kr][cc]);
                bf[nj][1] = __float_as_uint(Bs[buf][kr + 4][cc]);
            }
#pragma unroll
            for (int mi = 0; mi < 4; mi++)
#pragma unroll
                for (int nj = 0; nj < 4; nj++) {
                    asm("mma.sync.aligned.m16n8k8.row.col.f32.tf32.tf32.f32 "
                        "{%0,%1,%2,%3}, {%4,%5,%6,%7}, {%8,%9}, {%0,%1,%2,%3};"
                        : "+f"(c[mi][nj][0]), "+f"(c[mi][nj][1]),
                          "+f"(c[mi][nj][2]), "+f"(c[mi][nj][3])
                        : "r"(af[mi][0]), "r"(af[mi][1]),
                          "r"(af[mi][2]), "r"(af[mi][3]),
                          "r"(bf[nj][0]), "r"(bf[nj][1]));
                }
        }
        if (more) {
            int nb = buf ^ 1;
            float* as0 = &As[nb][ar_r][ac];
            as0[0] = tf32r(pa0.x); as0[1] = tf32r(pa0.y);
            as0[2] = tf32r(pa0.z); as0[3] = tf32r(pa0.w);
            float* as1 = &As[nb][ar_r + 64][ac];
            as1[0] = tf32r(pa1.x); as1[1] = tf32r(pa1.y);
            as1[2] = tf32r(pa1.z); as1[3] = tf32r(pa1.w);
            float* bs0 = &Bs[nb][br][bc];
            bs0[0] = tf32r(pb0.x); bs0[1] = tf32r(pb0.y);
            bs0[2] = tf32r(pb0.z); bs0[3] = tf32r(pb0.w);
            float* bs1 = &Bs[nb][br + 8][bc];
            bs1[0] = tf32r(pb1.x); bs1[1] = tf32r(pb1.y);
            bs1[2] = tf32r(pb1.z); bs1[3] = tf32r(pb1.w);
        }
        __syncthreads();
        buf ^= 1;
    }

    // al/ar values for this thread's 8 columns (head = warp_n)
    float alv[8], arv[8];
#pragma unroll
    for (int nj = 0; nj < 4; nj++) {
#pragma unroll
        for (int t = 0; t < 2; t++) {
            int col = warp_n * 32 + nj * 8 + (lane & 3) * 2 + t;
            alv[nj * 2 + t] = al[col];
            arv[nj * 2 + t] = ar[col];
        }
    }

    // epilogue: store C + fused el/er
#pragma unroll
    for (int mi = 0; mi < 4; mi++) {
        float sl0 = 0.f, sl1 = 0.f, sr0 = 0.f, sr1 = 0.f;
#pragma unroll
        for (int nj = 0; nj < 4; nj++) {
            int row0 = block_row + warp_m * 64 + mi * 16 + (lane >> 2);
            int col = warp_n * 32 + nj * 8 + (lane & 3) * 2;
            if (row0 < M)
                *(float2*)(C + (size_t)row0 * 128 + col) =
                    make_float2(c[mi][nj][0], c[mi][nj][1]);
            int row1 = row0 + 8;
            if (row1 < M)
                *(float2*)(C + (size_t)row1 * 128 + col) =
                    make_float2(c[mi][nj][2], c[mi][nj][3]);
            sl0 += c[mi][nj][0] * alv[nj * 2] + c[mi][nj][1] * alv[nj * 2 + 1];
            sl1 += c[mi][nj][2] * alv[nj * 2] + c[mi][nj][3] * alv[nj * 2 + 1];
            sr0 += c[mi][nj][0] * arv[nj * 2] + c[mi][nj][1] * arv[nj * 2 + 1];
            sr1 += c[mi][nj][2] * arv[nj * 2] + c[mi][nj][3] * arv[nj * 2 + 1];
        }
#pragma unroll
        for (int o = 1; o <= 2; o <<= 1) {
            sl0 += __shfl_xor_sync(0xffffffffu, sl0, o);
            sl1 += __shfl_xor_sync(0xffffffffu, sl1, o);
            sr0 += __shfl_xor_sync(0xffffffffu, sr0, o);
            sr1 += __shfl_xor_sync(0xffffffffu, sr1, o);
        }
        if ((lane & 3) == 0) {
            int row0 = block_row + warp_m * 64 + mi * 16 + (lane >> 2);
            int row1 = row0 + 8;
            if (row0 < M) {
                g_el[(size_t)row0 * 4 + warp_n] = sl0;
                g_er[(size_t)row0 * 4 + warp_n] = sr0;
            }
            if (row1 < M) {
                g_el[(size_t)row1 * 4 + warp_n] = sl1;
                g_er[(size_t)row1 * 4 + warp_n] = sr1;
            }
        }
    }
}

// ---------------- edge scores (no atomics) ----------------
__global__ void edge_score_kernel(const int* __restrict__ ei,
                                  float* __restrict__ ebuf,
                                  float* __restrict__ atten) {
    int e = blockIdx.x * blockDim.x + threadIdx.x;
    if (e >= EE) return;
    int s = ei[e], d = ei[EE + e];
    float4 l = *(const float4*)(g_el + (size_t)s * 4);
    float4 r = *(const float4*)(g_er + (size_t)d * 4);
    float z0 = l.x + r.x, z1 = l.y + r.y, z2 = l.z + r.z, z3 = l.w + r.w;
    z0 = z0 > 0.f ? z0 : SLOPE * z0;
    z1 = z1 > 0.f ? z1 : SLOPE * z1;
    z2 = z2 > 0.f ? z2 : SLOPE * z2;
    z3 = z3 > 0.f ? z3 : SLOPE * z3;
    *(float4*)(ebuf + (size_t)e * 4) = make_float4(z0, z1, z2, z3);
    atten[e] = 0.25f * (z0 + z1 + z2 + z3);
}

// ---------------- warp-per-node fused softmax + aggregate ----------------
// lane covers feats [lane*4, lane*4+4), head h = lane>>3.
template <int LAYER>
__global__ __launch_bounds__(256) void node_agg_kernel(const float* __restrict__ ebuf,
                                                       const float* __restrict__ feat,
                                                       float* __restrict__ out) {
    int node = blockIdx.x * (blockDim.x >> 5) + (threadIdx.x >> 5);
    if (node >= NN) return;
    int lane = threadIdx.x & 31;
    int beg = g_rowptr[node], end = g_rowptr[node + 1];

    // pass 1: per-head max
    float4 m = make_float4(NINF, NINF, NINF, NINF);
    for (int i = beg + lane; i < end; i += 32) {
        float4 z = *(const float4*)(ebuf + (size_t)g_csr_eid[i] * 4);
        m.x = fmaxf(m.x, z.x); m.y = fmaxf(m.y, z.y);
        m.z = fmaxf(m.z, z.z); m.w = fmaxf(m.w, z.w);
    }
#pragma unroll
    for (int o = 16; o; o >>= 1) {
        m.x = fmaxf(m.x, __shfl_xor_sync(0xffffffffu, m.x, o));
        m.y = fmaxf(m.y, __shfl_xor_sync(0xffffffffu, m.y, o));
        m.z = fmaxf(m.z, __shfl_xor_sync(0xffffffffu, m.z, o));
        m.w = fmaxf(m.w, __shfl_xor_sync(0xffffffffu, m.w, o));
    }

    // pass 2: per-head denom
    float4 s = make_float4(0.f, 0.f, 0.f, 0.f);
    for (int i = beg + lane; i < end; i += 32) {
        float4 z = *(const float4*)(ebuf + (size_t)g_csr_eid[i] * 4);
        s.x += __expf(z.x - m.x); s.y += __expf(z.y - m.y);
        s.z += __expf(z.z - m.z); s.w += __expf(z.w - m.w);
    }
#pragma unroll
    for (int o = 16; o; o >>= 1) {
        s.x += __shfl_xor_sync(0xffffffffu, s.x, o);
        s.y += __shfl_xor_sync(0xffffffffu, s.y, o);
        s.z += __shfl_xor_sync(0xffffffffu, s.z, o);
        s.w += __shfl_xor_sync(0xffffffffu, s.w, o);
    }

    int h = lane >> 3;
    float mh = (h == 0) ? m.x : (h == 1) ? m.y : (h == 2) ? m.z : m.w;
    float dh = (h == 0) ? s.x : (h == 1) ? s.y : (h == 2) ? s.z : s.w;
    float inv = dh > 0.f ? 1.f / dh : 0.f;

    // pass 3: weighted gather-accumulate (whole warp per edge)
    float4 acc = make_float4(0.f, 0.f, 0.f, 0.f);
    for (int i = beg; i < end; i++) {
        int src = g_csr_src[i];
        int eid = g_csr_eid[i];
        float zh = __ldg(ebuf + (size_t)eid * 4 + h);
        float a = __expf(zh - mh) * inv;
        float4 f = *(const float4*)(feat + (size_t)src * HD + lane * 4);
        acc.x += f.x * a; acc.y += f.y * a;
        acc.z += f.z * a; acc.w += f.w * a;
    }

    if (LAYER == 0) {
        acc.x = elu1(acc.x); acc.y = elu1(acc.y);
        acc.z = elu1(acc.z); acc.w = elu1(acc.w);
        *(float4*)(out + (size_t)node * HD + lane * 4) = acc;  // out = g_h1
    } else {
        float4 r = *(const float4*)(g_h1 + (size_t)node * HD + lane * 4);
        acc.x = elu1(acc.x + r.x); acc.y = elu1(acc.y + r.y);
        acc.z = elu1(acc.z + r.z); acc.w = elu1(acc.w + r.w);
        *(float4*)(out + (size_t)node * HD + lane * 4) = acc;  // temp [N,128]
        int d = (lane * 4) & 31;
        float* headp = out + (size_t)NN * HD + (size_t)h * NN * D + (size_t)node * D + d;
        *(float4*)headp = acc;
    }
}

static inline int cdiv(int a, int b) { return (a + b - 1) / b; }

extern "C" void kernel_launch(void* const* d_in, const int* in_sizes, int n_in,
                              void* d_out, int out_size) {
    const float* x   = (const float*)d_in[0];
    const int*   ei  = (const int*)d_in[1];
    const float* W0  = (const float*)d_in[2];
    const float* al0 = (const float*)d_in[3];
    const float* ar0 = (const float*)d_in[4];
    const float* W1  = (const float*)d_in[5];
    const float* al1 = (const float*)d_in[6];
    const float* ar1 = (const float*)d_in[7];
    float* out = (float*)d_out;

    float* e1_out = out + (size_t)NN * HD + (size_t)H * NN * D;  // [E, H]
    float* atten0 = e1_out + (size_t)EE * H;                     // [E]
    float* atten1 = atten0 + EE;                                 // [E]

    void *p_feat, *p_h1, *p_e0;
    cudaGetSymbolAddress(&p_feat, g_feat);
    cudaGetSymbolAddress(&p_h1, g_h1);
    cudaGetSymbolAddress(&p_e0, g_e0);
    float* feat = (float*)p_feat;
    float* h1   = (float*)p_h1;
    float* e0   = (float*)p_e0;

    const int T = 256;
    int g_gemm = cdiv(NN, 128);
    int g_edge = cdiv(EE, T);
    int g_node = cdiv(NN, T / 32);

    // CSR build interleaved with layer-0 GEMM (launch #4 = sgemm for ncu)
    zero_deg_kernel<<<cdiv(NN, T), T>>>();                       // 1
    count_deg_kernel<<<g_edge, T>>>(ei);                         // 2
    scan1_kernel<<<NBLK1, SCAN_BS>>>();                          // 3
    sgemm_tf32<<<g_gemm, T>>>(x, W0, al0, ar0, feat, NN, IN_DIM);// 4
    scan2_kernel<<<1, 256>>>();                                  // 5
    scan3_kernel<<<NBLK1, SCAN_BS>>>();                          // 6
    fill_csr_kernel<<<g_edge, T>>>(ei);                          // 7

    // layer 0
    edge_score_kernel<<<g_edge, T>>>(ei, e0, atten0);            // 8
    node_agg_kernel<0><<<g_node, T>>>(e0, feat, h1);             // 9

    // layer 1
    sgemm_tf32<<<g_gemm, T>>>(h1, W1, al1, ar1, feat, NN, HD);   // 10
    edge_score_kernel<<<g_edge, T>>>(ei, e1_out, atten1);        // 11
    node_agg_kernel<1><<<g_node, T>>>(e1_out, feat, out);        // 12
}

// round 4
// speedup vs baseline: 2.3527x; 1.0326x over previous
#include <cuda_runtime.h>
#include <cstdint>

#define NN 100000
#define EE 800000
#define IN_DIM 256
#define H 4
#define D 32
#define HD 128
#define SLOPE 0.2f
#define NINF (-3.402823466e38f)

// ---------------- scratch (no allocations allowed) ----------------
__device__ float g_feat[NN * HD];     // projected features of current layer
__device__ float g_h1[NN * HD];       // layer-0 output (residual for layer 1)
__device__ float g_el[NN * H];
__device__ float g_er[NN * H];
__device__ int   g_deg[NN];
__device__ int   g_rowptr[NN + 1];
__device__ int   g_cursor[NN];
__device__ int   g_partial[256];
__device__ int   g_csr_src[EE];
__device__ int   g_csr_eid[EE];

__device__ __forceinline__ float elu1(float x) {
    return x > 0.f ? x : expm1f(x);
}
__device__ __forceinline__ float tf32r(float x) {
    uint32_t u;
    asm("cvt.rna.tf32.f32 %0, %1;" : "=r"(u) : "f"(x));
    return __uint_as_float(u);
}
// exp with clamped argument (NaN/-inf safe for the online-softmax rescale)
__device__ __forceinline__ float expc(float a) {
    return __expf(fmaxf(a, -80.f));
}
__device__ __forceinline__ float lrelu(float x) {
    return x > 0.f ? x : SLOPE * x;
}

// ================= CSR build =================
__global__ void zero_deg_kernel() {
    int i = blockIdx.x * blockDim.x + threadIdx.x;
    if (i < NN) g_deg[i] = 0;
}

__global__ void count_deg_kernel(const int* __restrict__ ei) {
    int e = blockIdx.x * blockDim.x + threadIdx.x;
    if (e < EE) atomicAdd(&g_deg[ei[EE + e]], 1);
}

#define SCAN_BS 512
#define NBLK1 ((NN + SCAN_BS - 1) / SCAN_BS)   // 196

__global__ __launch_bounds__(SCAN_BS) void scan1_kernel() {
    __shared__ int s[SCAN_BS];
    int t = threadIdx.x;
    int i = blockIdx.x * SCAN_BS + t;
    int v = (i < NN) ? g_deg[i] : 0;
    s[t] = v;
    __syncthreads();
#pragma unroll
    for (int off = 1; off < SCAN_BS; off <<= 1) {
        int x = (t >= off) ? s[t - off] : 0;
        __syncthreads();
        s[t] += x;
        __syncthreads();
    }
    if (i < NN) g_rowptr[i] = s[t] - v;      // exclusive within block
    if (t == SCAN_BS - 1) g_partial[blockIdx.x] = s[t];
}

__global__ __launch_bounds__(256) void scan2_kernel() {
    __shared__ int s[256];
    int t = threadIdx.x;
    int v = (t < NBLK1) ? g_partial[t] : 0;
    s[t] = v;
    __syncthreads();
#pragma unroll
    for (int off = 1; off < 256; off <<= 1) {
        int x = (t >= off) ? s[t - off] : 0;
        __syncthreads();
        s[t] += x;
        __syncthreads();
    }
    if (t < NBLK1) g_partial[t] = s[t] - v;  // exclusive across blocks
}

__global__ __launch_bounds__(SCAN_BS) void scan3_kernel() {
    int t = threadIdx.x;
    int i = blockIdx.x * SCAN_BS + t;
    if (i < NN) {
        int r = g_rowptr[i] + g_partial[blockIdx.x];
        g_rowptr[i] = r;
        g_cursor[i] = r;
    }
    if (i == 0) g_rowptr[NN] = EE;
}

__global__ void fill_csr_kernel(const int* __restrict__ ei) {
    int e = blockIdx.x * blockDim.x + threadIdx.x;
    if (e >= EE) return;
    int s = ei[e], d = ei[EE + e];
    int pos = atomicAdd(&g_cursor[d], 1);
    g_csr_src[pos] = s;
    g_csr_eid[pos] = e;
}

// ========== TF32 tensor-core GEMM fused with attention dots ==========
#define AS_S 20
#define BS_S 136

__global__ __launch_bounds__(256, 2) void sgemm_tf32(const float* __restrict__ A,
                                                     const float* __restrict__ B,
                                                     const float* __restrict__ al,
                                                     const float* __restrict__ ar,
                                                     float* __restrict__ C,
                                                     int M, int K) {
    __shared__ float As[2][128][AS_S];
    __shared__ float Bs[2][16][BS_S];
    int tid = threadIdx.x;
    int lane = tid & 31;
    int wid = tid >> 5;
    int warp_m = wid & 1;
    int warp_n = wid >> 1;
    int block_row = blockIdx.x * 128;

    float c[4][4][4];
#pragma unroll
    for (int i = 0; i < 4; i++)
#pragma unroll
        for (int j = 0; j < 4; j++)
#pragma unroll
            for (int k = 0; k < 4; k++) c[i][j][k] = 0.f;

    int ar_r = tid >> 2;
    int ac = (tid & 3) * 4;
    int br = tid >> 5;
    int bc = (tid & 31) * 4;

    int gr0 = block_row + ar_r;
    int gr1 = gr0 + 64;
    bool v0 = gr0 < M, v1 = gr1 < M;
    const float* Ap0 = A + (size_t)gr0 * K;
    const float* Ap1 = A + (size_t)gr1 * K;

    int ntiles = K >> 4;
    float4 pa0, pa1, pb0, pb1;
    {
        pa0 = v0 ? *(const float4*)(Ap0 + ac) : make_float4(0, 0, 0, 0);
        pa1 = v1 ? *(const float4*)(Ap1 + ac) : make_float4(0, 0, 0, 0);
        pb0 = *(const float4*)(B + (size_t)br * 128 + bc);
        pb1 = *(const float4*)(B + (size_t)(br + 8) * 128 + bc);
        float* as0 = &As[0][ar_r][ac];
        as0[0] = tf32r(pa0.x); as0[1] = tf32r(pa0.y);
        as0[2] = tf32r(pa0.z); as0[3] = tf32r(pa0.w);
        float* as1 = &As[0][ar_r + 64][ac];
        as1[0] = tf32r(pa1.x); as1[1] = tf32r(pa1.y);
        as1[2] = tf32r(pa1.z); as1[3] = tf32r(pa1.w);
        float* bs0 = &Bs[0][br][bc];
        bs0[0] = tf32r(pb0.x); bs0[1] = tf32r(pb0.y);
        bs0[2] = tf32r(pb0.z); bs0[3] = tf32r(pb0.w);
        float* bs1 = &Bs[0][br + 8][bc];
        bs1[0] = tf32r(pb1.x); bs1[1] = tf32r(pb1.y);
        bs1[2] = tf32r(pb1.z); bs1[3] = tf32r(pb1.w);
    }
    __syncthreads();

    int buf = 0;
    for (int kt = 0; kt < ntiles; kt++) {
        bool more = (kt + 1) < ntiles;
        if (more) {
            int kb = (kt + 1) * 16;
            pa0 = v0 ? *(const float4*)(Ap0 + kb + ac) : make_float4(0, 0, 0, 0);
            pa1 = v1 ? *(const float4*)(Ap1 + kb + ac) : make_float4(0, 0, 0, 0);
            pb0 = *(const float4*)(B + (size_t)(kb + br) * 128 + bc);
            pb1 = *(const float4*)(B + (size_t)(kb + br + 8) * 128 + bc);
        }
#pragma unroll
        for (int ks = 0; ks < 2; ks++) {
            int k8 = ks * 8;
            uint32_t af[4][4];
            uint32_t bf[4][2];
#pragma unroll
            for (int mi = 0; mi < 4; mi++) {
                int r = warp_m * 64 + mi * 16 + (lane >> 2);
                int kc = k8 + (lane & 3);
                af[mi][0] = __float_as_uint(As[buf][r][kc]);
                af[mi][1] = __float_as_uint(As[buf][r + 8][kc]);
                af[mi][2] = __float_as_uint(As[buf][r][kc + 4]);
                af[mi][3] = __float_as_uint(As[buf][r + 8][kc + 4]);
            }
#pragma unroll
            for (int nj = 0; nj < 4; nj++) {
                int cc = warp_n * 32 + nj * 8 + (lane >> 2);
                int kr = k8 + (lane & 3);
                bf[nj][0] = __float_as_uint(Bs[buf][kr][cc]);
                bf[nj][1] = __float_as_uint(Bs[buf][kr + 4][cc]);
            }
#pragma unroll
            for (int mi = 0; mi < 4; mi++)
#pragma unroll
                for (int nj = 0; nj < 4; nj++) {
                    asm("mma.sync.aligned.m16n8k8.row.col.f32.tf32.tf32.f32 "
                        "{%0,%1,%2,%3}, {%4,%5,%6,%7}, {%8,%9}, {%0,%1,%2,%3};"
                        : "+f"(c[mi][nj][0]), "+f"(c[mi][nj][1]),
                          "+f"(c[mi][nj][2]), "+f"(c[mi][nj][3])
                        : "r"(af[mi][0]), "r"(af[mi][1]),
                          "r"(af[mi][2]), "r"(af[mi][3]),
                          "r"(bf[nj][0]), "r"(bf[nj][1]));
                }
        }
        if (more) {
            int nb = buf ^ 1;
            float* as0 = &As[nb][ar_r][ac];
            as0[0] = tf32r(pa0.x); as0[1] = tf32r(pa0.y);
            as0[2] = tf32r(pa0.z); as0[3] = tf32r(pa0.w);
            float* as1 = &As[nb][ar_r + 64][ac];
            as1[0] = tf32r(pa1.x); as1[1] = tf32r(pa1.y);
            as1[2] = tf32r(pa1.z); as1[3] = tf32r(pa1.w);
            float* bs0 = &Bs[nb][br][bc];
            bs0[0] = tf32r(pb0.x); bs0[1] = tf32r(pb0.y);
            bs0[2] = tf32r(pb0.z); bs0[3] = tf32r(pb0.w);
            float* bs1 = &Bs[nb][br + 8][bc];
            bs1[0] = tf32r(pb1.x); bs1[1] = tf32r(pb1.y);
            bs1[2] = tf32r(pb1.z); bs1[3] = tf32r(pb1.w);
        }
        __syncthreads();
        buf ^= 1;
    }

    float alv[8], arv[8];
#pragma unroll
    for (int nj = 0; nj < 4; nj++) {
#pragma unroll
        for (int t = 0; t < 2; t++) {
            int col = warp_n * 32 + nj * 8 + (lane & 3) * 2 + t;
            alv[nj * 2 + t] = al[col];
            arv[nj * 2 + t] = ar[col];
        }
    }

#pragma unroll
    for (int mi = 0; mi < 4; mi++) {
        float sl0 = 0.f, sl1 = 0.f, sr0 = 0.f, sr1 = 0.f;
#pragma unroll
        for (int nj = 0; nj < 4; nj++) {
            int row0 = block_row + warp_m * 64 + mi * 16 + (lane >> 2);
            int col = warp_n * 32 + nj * 8 + (lane & 3) * 2;
            if (row0 < M)
                *(float2*)(C + (size_t)row0 * 128 + col) =
                    make_float2(c[mi][nj][0], c[mi][nj][1]);
            int row1 = row0 + 8;
            if (row1 < M)
                *(float2*)(C + (size_t)row1 * 128 + col) =
                    make_float2(c[mi][nj][2], c[mi][nj][3]);
            sl0 += c[mi][nj][0] * alv[nj * 2] + c[mi][nj][1] * alv[nj * 2 + 1];
            sl1 += c[mi][nj][2] * alv[nj * 2] + c[mi][nj][3] * alv[nj * 2 + 1];
            sr0 += c[mi][nj][0] * arv[nj * 2] + c[mi][nj][1] * arv[nj * 2 + 1];
            sr1 += c[mi][nj][2] * arv[nj * 2] + c[mi][nj][3] * arv[nj * 2 + 1];
        }
#pragma unroll
        for (int o = 1; o <= 2; o <<= 1) {
            sl0 += __shfl_xor_sync(0xffffffffu, sl0, o);
            sl1 += __shfl_xor_sync(0xffffffffu, sl1, o);
            sr0 += __shfl_xor_sync(0xffffffffu, sr0, o);
            sr1 += __shfl_xor_sync(0xffffffffu, sr1, o);
        }
        if ((lane & 3) == 0) {
            int row0 = block_row + warp_m * 64 + mi * 16 + (lane >> 2);
            int row1 = row0 + 8;
            if (row0 < M) {
                g_el[(size_t)row0 * 4 + warp_n] = sl0;
                g_er[(size_t)row0 * 4 + warp_n] = sr0;
            }
            if (row1 < M) {
                g_el[(size_t)row1 * 4 + warp_n] = sl1;
                g_er[(size_t)row1 * 4 + warp_n] = sr1;
            }
        }
    }
}

// ---------------- edge scores for layer-1 outputs only ----------------
__global__ void edge_score_kernel(const int* __restrict__ ei,
                                  float* __restrict__ ebuf,
                                  float* __restrict__ atten) {
    int e = blockIdx.x * blockDim.x + threadIdx.x;
    if (e >= EE) return;
    int s = ei[e], d = ei[EE + e];
    float4 l = *(const float4*)(g_el + (size_t)s * 4);
    float4 r = *(const float4*)(g_er + (size_t)d * 4);
    float z0 = lrelu(l.x + r.x), z1 = lrelu(l.y + r.y);
    float z2 = lrelu(l.z + r.z), z3 = lrelu(l.w + r.w);
    *(float4*)(ebuf + (size_t)e * 4) = make_float4(z0, z1, z2, z3);
    atten[e] = 0.25f * (z0 + z1 + z2 + z3);
}

// ---------------- warp-per-node: inline scores + online softmax + agg ----
// pass 1 (lane-strided): z = leaky(el[src]+er[dst]); online (max,sum); the
// layer-0 variant also writes atten0[eid]. pass 2 (whole-warp per edge):
// a = exp(z_h - m_h)/s_h, gather feat[src], accumulate, residual+ELU+store.
template <int LAYER>
__global__ __launch_bounds__(256) void node_agg_kernel(const float* __restrict__ feat,
                                                       float* __restrict__ out,
                                                       float* __restrict__ atten) {
    int node = blockIdx.x * 8 + (threadIdx.x >> 5);
    if (node >= NN) return;
    int lane = threadIdx.x & 31;
    int beg = g_rowptr[node], end = g_rowptr[node + 1];
    float4 er = *(const float4*)(g_er + (size_t)node * 4);

    float4 m = make_float4(NINF, NINF, NINF, NINF);
    float4 s = make_float4(0.f, 0.f, 0.f, 0.f);
    for (int i = beg + lane; i < end; i += 32) {
        int src = g_csr_src[i];
        float4 l = *(const float4*)(g_el + (size_t)src * 4);
        float z0 = lrelu(l.x + er.x), z1 = lrelu(l.y + er.y);
        float z2 = lrelu(l.z + er.z), z3 = lrelu(l.w + er.w);
        if (LAYER == 0) atten[g_csr_eid[i]] = 0.25f * (z0 + z1 + z2 + z3);
        float4 mn;
        mn.x = fmaxf(m.x, z0); mn.y = fmaxf(m.y, z1);
        mn.z = fmaxf(m.z, z2); mn.w = fmaxf(m.w, z3);
        s.x = s.x * expc(m.x - mn.x) + __expf(z0 - mn.x);
        s.y = s.y * expc(m.y - mn.y) + __expf(z1 - mn.y);
        s.z = s.z * expc(m.z - mn.z) + __expf(z2 - mn.z);
        s.w = s.w * expc(m.w - mn.w) + __expf(z3 - mn.w);
        m = mn;
    }
#pragma unroll
    for (int o = 16; o; o >>= 1) {
        float4 mo, so, mn;
        mo.x = __shfl_xor_sync(0xffffffffu, m.x, o);
        mo.y = __shfl_xor_sync(0xffffffffu, m.y, o);
        mo.z = __shfl_xor_sync(0xffffffffu, m.z, o);
        mo.w = __shfl_xor_sync(0xffffffffu, m.w, o);
        so.x = __shfl_xor_sync(0xffffffffu, s.x, o);
        so.y = __shfl_xor_sync(0xffffffffu, s.y, o);
        so.z = __shfl_xor_sync(0xffffffffu, s.z, o);
        so.w = __shfl_xor_sync(0xffffffffu, s.w, o);
        mn.x = fmaxf(m.x, mo.x); mn.y = fmaxf(m.y, mo.y);
        mn.z = fmaxf(m.z, mo.z); mn.w = fmaxf(m.w, mo.w);
        s.x = s.x * expc(m.x - mn.x) + so.x * expc(mo.x - mn.x);
        s.y = s.y * expc(m.y - mn.y) + so.y * expc(mo.y - mn.y);
        s.z = s.z * expc(m.z - mn.z) + so.z * expc(mo.z - mn.z);
        s.w = s.w * expc(m.w - mn.w) + so.w * expc(mo.w - mn.w);
        m = mn;
    }

    int h = lane >> 3;
    float mh = (h == 0) ? m.x : (h == 1) ? m.y : (h == 2) ? m.z : m.w;
    float dh = (h == 0) ? s.x : (h == 1) ? s.y : (h == 2) ? s.z : s.w;
    float eh = (h == 0) ? er.x : (h == 1) ? er.y : (h == 2) ? er.z : er.w;
    float inv = dh > 0.f ? 1.f / dh : 0.f;

    float4 acc = make_float4(0.f, 0.f, 0.f, 0.f);
    for (int i = beg; i < end; i++) {
        int src = g_csr_src[i];
        float zh = lrelu(__ldg(g_el + (size_t)src * 4 + h) + eh);
        float a = __expf(zh - mh) * inv;
        float4 f = *(const float4*)(feat + (size_t)src * HD + lane * 4);
        acc.x += f.x * a; acc.y += f.y * a;
        acc.z += f.z * a; acc.w += f.w * a;
    }

    if (LAYER == 0) {
        acc.x = elu1(acc.x); acc.y = elu1(acc.y);
        acc.z = elu1(acc.z); acc.w = elu1(acc.w);
        *(float4*)(out + (size_t)node * HD + lane * 4) = acc;  // out = g_h1
    } else {
        float4 r = *(const float4*)(g_h1 + (size_t)node * HD + lane * 4);
        acc.x = elu1(acc.x + r.x); acc.y = elu1(acc.y + r.y);
        acc.z = elu1(acc.z + r.z); acc.w = elu1(acc.w + r.w);
        *(float4*)(out + (size_t)node * HD + lane * 4) = acc;  // temp [N,128]
        int d = (lane * 4) & 31;
        float* headp = out + (size_t)NN * HD + (size_t)h * NN * D + (size_t)node * D + d;
        *(float4*)headp = acc;
    }
}

static inline int cdiv(int a, int b) { return (a + b - 1) / b; }

extern "C" void kernel_launch(void* const* d_in, const int* in_sizes, int n_in,
                              void* d_out, int out_size) {
    const float* x   = (const float*)d_in[0];
    const int*   ei  = (const int*)d_in[1];
    const float* W0  = (const float*)d_in[2];
    const float* al0 = (const float*)d_in[3];
    const float* ar0 = (const float*)d_in[4];
    const float* W1  = (const float*)d_in[5];
    const float* al1 = (const float*)d_in[6];
    const float* ar1 = (const float*)d_in[7];
    float* out = (float*)d_out;

    float* e1_out = out + (size_t)NN * HD + (size_t)H * NN * D;  // [E, H]
    float* atten0 = e1_out + (size_t)EE * H;                     // [E]
    float* atten1 = atten0 + EE;                                 // [E]

    void *p_feat, *p_h1;
    cudaGetSymbolAddress(&p_feat, g_feat);
    cudaGetSymbolAddress(&p_h1, g_h1);
    float* feat = (float*)p_feat;
    float* h1   = (float*)p_h1;

    const int T = 256;
    int g_gemm = cdiv(NN, 128);
    int g_edge = cdiv(EE, T);
    int g_node = cdiv(NN, 8);

    cudaStream_t side;
    cudaStreamCreateWithFlags(&side, cudaStreamNonBlocking);
    cudaEvent_t evFork0, evJoin0, evFork1, evJoin1;
    cudaEventCreateWithFlags(&evFork0, cudaEventDisableTiming);
    cudaEventCreateWithFlags(&evJoin0, cudaEventDisableTiming);
    cudaEventCreateWithFlags(&evFork1, cudaEventDisableTiming);
    cudaEventCreateWithFlags(&evJoin1, cudaEventDisableTiming);

    // ---- fork: CSR build on side stream, concurrent with layer-0 GEMM ----
    cudaEventRecord(evFork0, 0);
    cudaStreamWaitEvent(side, evFork0, 0);
    zero_deg_kernel<<<cdiv(NN, T), T, 0, side>>>();
    count_deg_kernel<<<g_edge, T, 0, side>>>(ei);
    scan1_kernel<<<NBLK1, SCAN_BS, 0, side>>>();
    scan2_kernel<<<1, 256, 0, side>>>();
    scan3_kernel<<<NBLK1, SCAN_BS, 0, side>>>();
    fill_csr_kernel<<<g_edge, T, 0, side>>>(ei);
    cudaEventRecord(evJoin0, side);

    sgemm_tf32<<<g_gemm, T>>>(x, W0, al0, ar0, feat, NN, IN_DIM);

    // ---- join: node_agg<0> needs both CSR and GEMM0 ----
    cudaStreamWaitEvent(0, evJoin0, 0);
    node_agg_kernel<0><<<g_node, T>>>(feat, h1, atten0);

    // ---- layer 1 ----
    sgemm_tf32<<<g_gemm, T>>>(h1, W1, al1, ar1, feat, NN, HD);

    // fork: e1/atten1 writes concurrent with node_agg<1>
    cudaEventRecord(evFork1, 0);
    cudaStreamWaitEvent(side, evFork1, 0);
    edge_score_kernel<<<g_edge, T, 0, side>>>(ei, e1_out, atten1);
    cudaEventRecord(evJoin1, side);

    node_agg_kernel<1><<<g_node, T>>>(feat, out, nullptr);
    cudaStreamWaitEvent(0, evJoin1, 0);
}